// round 4
// baseline (speedup 1.0000x reference)
#include <cuda_runtime.h>
#include <cstdint>

#define BB    512
#define DD    128
#define SS    50
#define TT    32
#define LL    64
#define CLIPF 50
#define NF    10000

#define BAR_GRP(id) asm volatile("bar.sync %0, 128;" :: "r"(id) : "memory")

// ---------------------------------------------------------------
// One block per batch element. block = 256 = 2 groups x 128 threads.
// Group g processes sentences s = g, g+2, ..., keeping everything
// (mem, sentence[50][128], sw[50]) in shared memory across 2 hoops,
// then runs the final stage in-block. Single kernel launch.
// ---------------------------------------------------------------
__global__ void __launch_bounds__(256)
k_fused(const int* __restrict__ user_idx,
        const int* __restrict__ item_idx,
        const float* __restrict__ emb_word,
        const float* __restrict__ emb_item,
        const float* __restrict__ emb_user,
        const float* __restrict__ W_mem, const float* __restrict__ b_mem,
        const float* __restrict__ w_word, const float* __restrict__ b_word,
        const float* __restrict__ w_sent, const float* __restrict__ b_sent,
        const float* __restrict__ W_tr,  const float* __restrict__ b_tr,
        const float* __restrict__ W1,  const float* __restrict__ b1,
        const float* __restrict__ W2,  const float* __restrict__ b2,
        const float* __restrict__ W3,  const float* __restrict__ b3,
        const float* __restrict__ w_aff, const float* __restrict__ b_aff,
        const int* __restrict__ uti,
        const int* __restrict__ ufi,
        float* __restrict__ out) {
    int b    = blockIdx.x;
    int tid  = threadIdx.x;
    int grp  = tid >> 7;         // 0 or 1
    int gt   = tid & 127;        // thread within group
    int lane = tid & 31;
    int warpg = gt >> 5;         // warp within group, 0..3

    __shared__ __align__(16) float mem_s[DD];
    __shared__ __align__(16) float sent_s[SS][DD];   // 25.6 KB
    __shared__ float sw_s[SS];
    __shared__ float sc[2][TT];
    __shared__ __align__(16) float part[2][4][DD];
    __shared__ float wred[2][4];
    __shared__ float it64[LL];
    __shared__ float iw_sh;
    __shared__ float swf[SS];
    // final-stage scratch
    __shared__ float a1[32], a2[16], alpha[2];
    __shared__ float upart[2][LL];
    __shared__ float red2[2];
    __shared__ int   padc[2];

    int u = user_idx[b];

    // ---- init: mem = emb_item[item] @ W_mem + b_mem ----
    if (tid < LL) it64[tid] = emb_item[(size_t)item_idx[b] * LL + tid];
    __syncthreads();
    if (tid < DD) {
        float acc = b_mem[tid];
#pragma unroll
        for (int l = 0; l < LL; l++) acc += it64[l] * W_mem[l * DD + tid];
        mem_s[tid] = acc;
    }
    __syncthreads();

    // ---- two hoops ----
    for (int hoop = 0; hoop < 2; hoop++) {
        // lane's slice of mem (d = 4*lane .. 4*lane+3)
        float4 m4 = reinterpret_cast<const float4*>(mem_s)[lane];

        for (int s = grp; s < SS; s += 2) {
            const int* idxp = uti + ((size_t)u * SS + s) * TT + warpg * 8;
            int widx[8];
#pragma unroll
            for (int k = 0; k < 8; k++) widx[k] = idxp[k];
            float4 r[8];
#pragma unroll
            for (int k = 0; k < 8; k++)
                r[k] = reinterpret_cast<const float4*>(emb_word + (size_t)widx[k] * DD)[lane];

            // scores: in-register dot + shuffle reduce
#pragma unroll
            for (int k = 0; k < 8; k++) {
                float p = r[k].x * m4.x + r[k].y * m4.y + r[k].z * m4.z + r[k].w * m4.w;
#pragma unroll
                for (int o = 16; o; o >>= 1) p += __shfl_xor_sync(0xffffffffu, p, o);
                if (lane == 0) sc[grp][warpg * 8 + k] = p;
            }
            BAR_GRP(grp + 1);

            // softmax over T=32 (warp 0 of group)
            if (warpg == 0) {
                float v = sc[grp][lane];
                float mx = v;
#pragma unroll
                for (int o = 16; o; o >>= 1) mx = fmaxf(mx, __shfl_xor_sync(0xffffffffu, mx, o));
                float e = expf(v - mx);
                float sum = e;
#pragma unroll
                for (int o = 16; o; o >>= 1) sum += __shfl_xor_sync(0xffffffffu, sum, o);
                sc[grp][lane] = e / sum;
            }
            BAR_GRP(grp + 1);

            // weighted sum in registers
            float4 acc = make_float4(0.f, 0.f, 0.f, 0.f);
#pragma unroll
            for (int k = 0; k < 8; k++) {
                float wk = sc[grp][warpg * 8 + k];
                acc.x += wk * r[k].x;
                acc.y += wk * r[k].y;
                acc.z += wk * r[k].z;
                acc.w += wk * r[k].w;
            }
            reinterpret_cast<float4*>(&part[grp][warpg][0])[lane] = acc;
            BAR_GRP(grp + 1);

            float sd = part[grp][0][gt] + part[grp][1][gt]
                     + part[grp][2][gt] + part[grp][3][gt];
            sent_s[s][gt] = sd;

            // sw = sentence . w_word + b_word
            float p = sd * w_word[gt];
#pragma unroll
            for (int o = 16; o; o >>= 1) p += __shfl_xor_sync(0xffffffffu, p, o);
            if (lane == 0) wred[grp][warpg] = p;
            BAR_GRP(grp + 1);
            if (gt == 0)
                sw_s[s] = wred[grp][0] + wred[grp][1] + wred[grp][2] + wred[grp][3] + b_word[0];
        }
        __syncthreads();   // all sentences done, sw_s/sent_s complete

        // ---- sentence-level attention (in-block) ----
        if (tid < 32) {
            // iw = mem . w_sent + b_sent  (warp 0)
            float4 mm = reinterpret_cast<const float4*>(mem_s)[lane];
            float4 ws = reinterpret_cast<const float4*>(w_sent)[lane];
            float p = mm.x * ws.x + mm.y * ws.y + mm.z * ws.z + mm.w * ws.w;
#pragma unroll
            for (int o = 16; o; o >>= 1) p += __shfl_xor_sync(0xffffffffu, p, o);
            float iw = p + b_sent[0];

            float v0 = (lane < SS)      ? tanhf(sw_s[lane] + iw)      : -1e30f;
            float v1 = (lane + 32 < SS) ? tanhf(sw_s[lane + 32] + iw) : -1e30f;
            float mx = fmaxf(v0, v1);
#pragma unroll
            for (int o = 16; o; o >>= 1) mx = fmaxf(mx, __shfl_xor_sync(0xffffffffu, mx, o));
            float e0 = (lane < SS)      ? expf(v0 - mx) : 0.f;
            float e1 = (lane + 32 < SS) ? expf(v1 - mx) : 0.f;
            float sum = e0 + e1;
#pragma unroll
            for (int o = 16; o; o >>= 1) sum += __shfl_xor_sync(0xffffffffu, sum, o);
            if (lane < SS)      swf[lane]      = e0 / sum;
            if (lane + 32 < SS) swf[lane + 32] = e1 / sum;
        }
        __syncthreads();

        // mem += sum_s swf[s] * sentence[s,:]
        if (tid < DD) {
            float acc = mem_s[tid];
#pragma unroll 5
            for (int s = 0; s < SS; s++) acc += swf[s] * sent_s[s][tid];
            mem_s[tid] = acc;
        }
        __syncthreads();
    }

    // ---- final stage (threads 0..63 = 2 warps) ----
    float it = 0.f, ept = 0.f;
    if (tid < LL) {
        it = it64[tid];
        ept = b_tr[tid];
#pragma unroll 8
        for (int d = 0; d < DD; d++) ept += mem_s[d] * W_tr[d * LL + tid];
        if (tid < 32) {
            float a = b1[tid];
#pragma unroll
            for (int k = 0; k < LL; k++) a += it64[k] * W1[k * 32 + tid];
            a1[tid] = 1.f / (1.f + expf(-a));
        }
    }
    __syncthreads();
    if (tid < 16) {
        float a = b2[tid];
#pragma unroll
        for (int k = 0; k < 32; k++) a += a1[k] * W2[k * 16 + tid];
        a2[tid] = 1.f / (1.f + expf(-a));
    }
    __syncthreads();
    if (tid < 2) {
        float a = b3[tid];
#pragma unroll
        for (int k = 0; k < 16; k++) a += a2[k] * W3[k * 2 + tid];
        alpha[tid] = 1.f / (1.f + expf(-a));
    }

    // friend aggregation: warps 0,1 (tid < 64)
    if (tid < 64) {
        int w2 = tid >> 5;
        const int* fp = ufi + (size_t)u * CLIPF;
        float ba = b_aff[0];
        float i0 = it64[lane],   i1 = it64[lane + 32];
        float w0 = w_aff[lane],  w1 = w_aff[lane + 32];
        float ua0 = 0.f, ua1 = 0.f;
        int pcount = 0;
        for (int c = w2; c < CLIPF; c += 2) {
            int f = fp[c];
            if (f == NF && lane == 0) pcount++;
            const float* fr = emb_user + (size_t)f * LL;
            float f0 = fr[lane], f1 = fr[lane + 32];
            float p = i0 * f0 * w0 + i1 * f1 * w1;
#pragma unroll
            for (int o = 16; o; o >>= 1) p += __shfl_xor_sync(0xffffffffu, p, o);
            float g = 1.f / (1.f + expf(-(p + ba)));
            if (lane == 0) out[BB + (size_t)b * CLIPF + c] = g;
            ua0 += f0 * g;
            ua1 += f1 * g;
        }
        upart[w2][lane] = ua0;
        upart[w2][lane + 32] = ua1;
        if (lane == 0) padc[w2] = pcount;
    }
    __syncthreads();
    if (tid < 64) {
        int w2 = tid >> 5;
        float fn = (float)CLIPF - (float)(padc[0] + padc[1]);
        float ue = (upart[0][tid] + upart[1][tid]) / fn;
        float vec = alpha[0] * ept + alpha[1] * ue;
        float p = vec * it * w_aff[tid];
#pragma unroll
        for (int o = 16; o; o >>= 1) p += __shfl_xor_sync(0xffffffffu, p, o);
        if (lane == 0) red2[w2] = p;
    }
    __syncthreads();
    if (tid == 0)
        out[b] = 1.f / (1.f + expf(-(red2[0] + red2[1] + b_aff[0])));
}

// ---------------------------------------------------------------
extern "C" void kernel_launch(void* const* d_in, const int* in_sizes, int n_in,
                              void* d_out, int out_size) {
    const int*   user_idx = (const int*)d_in[0];
    const int*   item_idx = (const int*)d_in[1];
    const float* emb_word = (const float*)d_in[2];
    const float* emb_item = (const float*)d_in[3];
    const float* emb_user = (const float*)d_in[4];
    const float* W_mem    = (const float*)d_in[5];
    const float* b_mem    = (const float*)d_in[6];
    const float* w_word   = (const float*)d_in[7];
    const float* b_word   = (const float*)d_in[8];
    const float* w_sent   = (const float*)d_in[9];
    const float* b_sent   = (const float*)d_in[10];
    const float* W_tr     = (const float*)d_in[11];
    const float* b_tr     = (const float*)d_in[12];
    const float* W1       = (const float*)d_in[13];
    const float* b1       = (const float*)d_in[14];
    const float* W2       = (const float*)d_in[15];
    const float* b2       = (const float*)d_in[16];
    const float* W3       = (const float*)d_in[17];
    const float* b3       = (const float*)d_in[18];
    const float* w_aff    = (const float*)d_in[19];
    const float* b_aff    = (const float*)d_in[20];
    const int*   uti      = (const int*)d_in[21];
    const int*   ufi      = (const int*)d_in[22];
    float* out = (float*)d_out;

    k_fused<<<BB, 256>>>(user_idx, item_idx, emb_word, emb_item, emb_user,
                         W_mem, b_mem, w_word, b_word, w_sent, b_sent,
                         W_tr, b_tr, W1, b1, W2, b2, W3, b3,
                         w_aff, b_aff, uti, ufi, out);
}

// round 5
// speedup vs baseline: 1.6491x; 1.6491x over previous
#include <cuda_runtime.h>
#include <cstdint>

#define BB    512
#define DD    128
#define SS    50
#define TT    32
#define LL    64
#define CLIPF 50
#define NF    10000

// ---- device scratch (no allocations allowed) ----
__device__ __align__(16) float g_mem[BB * DD];                // [B, D]
__device__ __align__(16) float g_sent[(size_t)BB * SS * DD];  // [B, S, D]
__device__ float g_sw[BB * SS];                               // [B, S]

// merge-exchange: lanes with (lane&bit)==0 end holding a(l)+a(l^bit),
// lanes with (lane&bit)!=0 end holding b(l)+b(l^bit). One SHFL.
__device__ __forceinline__ float merge2(float a, float b, int bit, int lane) {
    float t = (lane & bit) ? a : b;
    float u = __shfl_xor_sync(0xffffffffu, t, bit);
    return ((lane & bit) ? b : a) + u;
}

// ---------------------------------------------------------------
// mem = emb_item[item] @ W_mem + b_mem      grid=B, block=D
// ---------------------------------------------------------------
__global__ void k_init_mem(const int* __restrict__ item_idx,
                           const float* __restrict__ emb_item,
                           const float* __restrict__ W_mem,
                           const float* __restrict__ b_mem) {
    int b = blockIdx.x, d = threadIdx.x;
    __shared__ float it_s[LL];
    if (d < LL) it_s[d] = emb_item[(size_t)item_idx[b] * LL + d];
    __syncthreads();
    float acc = b_mem[d];
#pragma unroll
    for (int l = 0; l < LL; l++) acc += it_s[l] * W_mem[l * DD + d];
    g_mem[b * DD + d] = acc;
}

// ---------------------------------------------------------------
// Word-level attention, register tile, 2 barriers, 23-shfl scores.
// grid = (B, S), block = 128. Warp w owns rows t in [8w, 8w+8);
// lane holds d = 4*lane..4*lane+3 as float4.
// ---------------------------------------------------------------
__global__ void __launch_bounds__(128)
k_word_attn(const int* __restrict__ user_idx,
            const int* __restrict__ uti,
            const float* __restrict__ emb_word,
            const float* __restrict__ w_word,
            const float* __restrict__ b_word) {
    int b = blockIdx.x, s = blockIdx.y;
    int tid = threadIdx.x, lane = tid & 31, warp = tid >> 5;

    __shared__ float sc[TT];               // scores
    __shared__ __align__(16) float part[4][DD]; // per-warp sentence partials
    __shared__ float wred[4];

    float4 m4 = reinterpret_cast<const float4*>(g_mem + b * DD)[lane];

    int u = user_idx[b];
    const int* idxp = uti + ((size_t)u * SS + s) * TT + warp * 8;

    int widx[8];
#pragma unroll
    for (int k = 0; k < 8; k++) widx[k] = idxp[k];

    float4 r[8];
#pragma unroll
    for (int k = 0; k < 8; k++)
        r[k] = reinterpret_cast<const float4*>(emb_word + (size_t)widx[k] * DD)[lane];

    // per-lane partial dots for the 8 rows
    float p[8];
#pragma unroll
    for (int k = 0; k < 8; k++)
        p[k] = r[k].x * m4.x + r[k].y * m4.y + r[k].z * m4.z + r[k].w * m4.w;

    // stage A: full butterflies xor16, xor8 on all 8 values (16 SHFL)
#pragma unroll
    for (int off = 16; off >= 8; off >>= 1) {
#pragma unroll
        for (int k = 0; k < 8; k++)
            p[k] += __shfl_xor_sync(0xffffffffu, p[k], off);
    }
    // stage B: merge-exchange down to 1 value per lane (7 SHFL)
    float q0 = merge2(p[0], p[1], 4, lane);
    float q1 = merge2(p[2], p[3], 4, lane);
    float q2 = merge2(p[4], p[5], 4, lane);
    float q3 = merge2(p[6], p[7], 4, lane);
    float r0 = merge2(q0, q1, 2, lane);
    float r1 = merge2(q2, q3, 2, lane);
    float s0 = merge2(r0, r1, 1, lane);
    if (lane < 8) {
        int k = ((lane >> 2) & 1) | (lane & 2) | ((lane & 1) << 2);
        sc[warp * 8 + k] = s0;
    }
    __syncthreads();   // barrier 1: scores complete

    // softmax over T=32, computed redundantly in every warp
    float v = sc[lane];
    float mx = v;
#pragma unroll
    for (int o = 16; o; o >>= 1) mx = fmaxf(mx, __shfl_xor_sync(0xffffffffu, mx, o));
    float e = __expf(v - mx);
    float sum = e;
#pragma unroll
    for (int o = 16; o; o >>= 1) sum += __shfl_xor_sync(0xffffffffu, sum, o);
    float inv = __fdividef(1.f, sum);

    // weighted sum in registers
    float4 acc = make_float4(0.f, 0.f, 0.f, 0.f);
#pragma unroll
    for (int k = 0; k < 8; k++) {
        float wk = __shfl_sync(0xffffffffu, e, warp * 8 + k) * inv;
        acc.x += wk * r[k].x;
        acc.y += wk * r[k].y;
        acc.z += wk * r[k].z;
        acc.w += wk * r[k].w;
    }
    reinterpret_cast<float4*>(&part[warp][0])[lane] = acc;

    // fold sw partial into the same barrier: sw = sum_w dot(part_w, w_word)
    float4 ww4 = reinterpret_cast<const float4*>(w_word)[lane];
    float pw = acc.x * ww4.x + acc.y * ww4.y + acc.z * ww4.z + acc.w * ww4.w;
#pragma unroll
    for (int o = 16; o; o >>= 1) pw += __shfl_xor_sync(0xffffffffu, pw, o);
    if (lane == 0) wred[warp] = pw;
    __syncthreads();   // barrier 2: partials + wred complete

    // final sentence[d], d = tid
    float sd = part[0][tid] + part[1][tid] + part[2][tid] + part[3][tid];
    g_sent[((size_t)b * SS + s) * DD + tid] = sd;

    if (tid == 0)
        g_sw[b * SS + s] = wred[0] + wred[1] + wred[2] + wred[3] + b_word[0];
}

// ---------------------------------------------------------------
// Sentence-level attention + mem update.  grid=B, block=128
// ---------------------------------------------------------------
__global__ void k_sent_attn(const float* __restrict__ w_sent,
                            const float* __restrict__ b_sent) {
    int b = blockIdx.x, tid = threadIdx.x, lane = tid & 31, warp = tid >> 5;
    __shared__ float wred[4];
    __shared__ float swf[SS];
    __shared__ float iw_s;

    float m = g_mem[b * DD + tid];

    // iw = mem . w_sent + b_sent
    float p = m * w_sent[tid];
#pragma unroll
    for (int o = 16; o; o >>= 1) p += __shfl_xor_sync(0xffffffffu, p, o);
    if (lane == 0) wred[warp] = p;
    __syncthreads();
    if (tid == 0) iw_s = wred[0] + wred[1] + wred[2] + wred[3] + b_sent[0];
    __syncthreads();

    // softmax over S of tanh(sw + iw)  (warp 0)
    if (warp == 0) {
        float iw = iw_s;
        float v0 = (lane < SS)      ? tanhf(g_sw[b * SS + lane] + iw)        : -1e30f;
        float v1 = (lane + 32 < SS) ? tanhf(g_sw[b * SS + lane + 32] + iw)   : -1e30f;
        float mx = fmaxf(v0, v1);
#pragma unroll
        for (int o = 16; o; o >>= 1) mx = fmaxf(mx, __shfl_xor_sync(0xffffffffu, mx, o));
        float e0 = (lane < SS)      ? __expf(v0 - mx) : 0.f;
        float e1 = (lane + 32 < SS) ? __expf(v1 - mx) : 0.f;
        float sum = e0 + e1;
#pragma unroll
        for (int o = 16; o; o >>= 1) sum += __shfl_xor_sync(0xffffffffu, sum, o);
        float inv = __fdividef(1.f, sum);
        if (lane < SS)      swf[lane]      = e0 * inv;
        if (lane + 32 < SS) swf[lane + 32] = e1 * inv;
    }
    __syncthreads();

    // mem += sum_s swf[s] * sentence[b,s,:]
    float acc = m;
    const float* sp = g_sent + (size_t)b * SS * DD + tid;
#pragma unroll 5
    for (int s = 0; s < SS; s++) acc += swf[s] * sp[s * DD];
    g_mem[b * DD + tid] = acc;
}

// ---------------------------------------------------------------
// Final stage: ept, friend aggregation + group_idx, alpha MLP, rating.
// grid=B, block=64 (=L)
// ---------------------------------------------------------------
__global__ void k_final(const int* __restrict__ user_idx,
                        const int* __restrict__ item_idx,
                        const float* __restrict__ emb_item,
                        const float* __restrict__ emb_user,
                        const float* __restrict__ W_tr, const float* __restrict__ b_tr,
                        const float* __restrict__ W1,  const float* __restrict__ b1,
                        const float* __restrict__ W2,  const float* __restrict__ b2,
                        const float* __restrict__ W3,  const float* __restrict__ b3,
                        const float* __restrict__ w_aff, const float* __restrict__ b_aff,
                        const int* __restrict__ ufi,
                        float* __restrict__ out) {
    int b = blockIdx.x, l = threadIdx.x, lane = l & 31, warp = l >> 5;
    __shared__ float item_s[LL], a1[32], a2[16], alpha[2];
    __shared__ float upart[2][LL];
    __shared__ float red2[2];
    __shared__ int padc[2];

    float it = emb_item[(size_t)item_idx[b] * LL + l];
    item_s[l] = it;
    float waff_l = w_aff[l];
    float ba = b_aff[0];

    // ept[l] = mem[b] @ W_tr[:, l] + b_tr[l]
    float ept = b_tr[l];
    const float* memp = g_mem + b * DD;
#pragma unroll 8
    for (int d = 0; d < DD; d++) ept += memp[d] * W_tr[d * LL + l];
    __syncthreads();

    // alpha MLP
    if (l < 32) {
        float a = b1[l];
#pragma unroll
        for (int k = 0; k < LL; k++) a += item_s[k] * W1[k * 32 + l];
        a1[l] = 1.f / (1.f + __expf(-a));
    }
    __syncthreads();
    if (l < 16) {
        float a = b2[l];
#pragma unroll
        for (int k = 0; k < 32; k++) a += a1[k] * W2[k * 16 + l];
        a2[l] = 1.f / (1.f + __expf(-a));
    }
    __syncthreads();
    if (l < 2) {
        float a = b3[l];
#pragma unroll
        for (int k = 0; k < 16; k++) a += a2[k] * W3[k * 2 + l];
        alpha[l] = 1.f / (1.f + __expf(-a));
    }

    // friend aggregation: warp w handles friends c = w, w+2, ...
    int u = user_idx[b];
    const int* fp = ufi + (size_t)u * CLIPF;
    float i0 = item_s[lane],       i1 = item_s[lane + 32];
    float w0 = w_aff[lane],        w1 = w_aff[lane + 32];
    float ua0 = 0.f, ua1 = 0.f;
    int pcount = 0;
    for (int c = warp; c < CLIPF; c += 2) {
        int f = fp[c];
        if (f == NF && lane == 0) pcount++;
        const float* fr = emb_user + (size_t)f * LL;
        float f0 = fr[lane], f1 = fr[lane + 32];
        float p = i0 * f0 * w0 + i1 * f1 * w1;
#pragma unroll
        for (int o = 16; o; o >>= 1) p += __shfl_xor_sync(0xffffffffu, p, o);
        float g = 1.f / (1.f + __expf(-(p + ba)));
        if (lane == 0) out[BB + (size_t)b * CLIPF + c] = g;
        ua0 += f0 * g;
        ua1 += f1 * g;
    }
    upart[warp][lane] = ua0;
    upart[warp][lane + 32] = ua1;
    if (lane == 0) padc[warp] = pcount;
    __syncthreads();

    float fn = (float)CLIPF - (float)(padc[0] + padc[1]);
    float ue = (upart[0][l] + upart[1][l]) / fn;

    float vec = alpha[0] * ept + alpha[1] * ue;
    float p = vec * it * waff_l;
#pragma unroll
    for (int o = 16; o; o >>= 1) p += __shfl_xor_sync(0xffffffffu, p, o);
    if (lane == 0) red2[warp] = p;
    __syncthreads();
    if (l == 0) out[b] = 1.f / (1.f + __expf(-(red2[0] + red2[1] + ba)));
}

// ---------------------------------------------------------------
extern "C" void kernel_launch(void* const* d_in, const int* in_sizes, int n_in,
                              void* d_out, int out_size) {
    const int*   user_idx = (const int*)d_in[0];
    const int*   item_idx = (const int*)d_in[1];
    const float* emb_word = (const float*)d_in[2];
    const float* emb_item = (const float*)d_in[3];
    const float* emb_user = (const float*)d_in[4];
    const float* W_mem    = (const float*)d_in[5];
    const float* b_mem    = (const float*)d_in[6];
    const float* w_word   = (const float*)d_in[7];
    const float* b_word   = (const float*)d_in[8];
    const float* w_sent   = (const float*)d_in[9];
    const float* b_sent   = (const float*)d_in[10];
    const float* W_tr     = (const float*)d_in[11];
    const float* b_tr     = (const float*)d_in[12];
    const float* W1       = (const float*)d_in[13];
    const float* b1       = (const float*)d_in[14];
    const float* W2       = (const float*)d_in[15];
    const float* b2       = (const float*)d_in[16];
    const float* W3       = (const float*)d_in[17];
    const float* b3       = (const float*)d_in[18];
    const float* w_aff    = (const float*)d_in[19];
    const float* b_aff    = (const float*)d_in[20];
    const int*   uti      = (const int*)d_in[21];
    const int*   ufi      = (const int*)d_in[22];
    float* out = (float*)d_out;

    k_init_mem<<<BB, DD>>>(item_idx, emb_item, W_mem, b_mem);
    dim3 gA(BB, SS);
    for (int h = 0; h < 2; h++) {
        k_word_attn<<<gA, 128>>>(user_idx, uti, emb_word, w_word, b_word);
        k_sent_attn<<<BB, 128>>>(w_sent, b_sent);
    }
    k_final<<<BB, LL>>>(user_idx, item_idx, emb_item, emb_user,
                        W_tr, b_tr, W1, b1, W2, b2, W3, b3,
                        w_aff, b_aff, ufi, out);
}

// round 7
// speedup vs baseline: 2.0766x; 1.2593x over previous
#include <cuda_runtime.h>
#include <cstdint>

#define BB    512
#define DD    128
#define SS    50
#define TT    32
#define LL    64
#define CLIPF 50
#define NF    10000

// ---- device scratch (no allocations allowed) ----
__device__ __align__(16) float g_mem[BB * DD];                // [B, D]
__device__ __align__(16) float g_sent[(size_t)BB * SS * DD];  // [B, S, D]
__device__ float g_sw[BB * SS];                               // [B, S]

// merge-exchange: lanes with (lane&bit)==0 end holding a(l)+a(l^bit),
// lanes with (lane&bit)!=0 end holding b(l)+b(l^bit). One SHFL.
__device__ __forceinline__ float merge2(float a, float b, int bit, int lane) {
    float t = (lane & bit) ? a : b;
    float u = __shfl_xor_sync(0xffffffffu, t, bit);
    return ((lane & bit) ? b : a) + u;
}

// ---------------------------------------------------------------
// mem = emb_item[item] @ W_mem + b_mem      grid=B, block=D
// ---------------------------------------------------------------
__global__ void k_init_mem(const int* __restrict__ item_idx,
                           const float* __restrict__ emb_item,
                           const float* __restrict__ W_mem,
                           const float* __restrict__ b_mem) {
    int b = blockIdx.x, d = threadIdx.x;
    __shared__ float it_s[LL];
    if (d < LL) it_s[d] = emb_item[(size_t)item_idx[b] * LL + d];
    __syncthreads();
    float acc = b_mem[d];
#pragma unroll
    for (int l = 0; l < LL; l++) acc += it_s[l] * W_mem[l * DD + d];
    g_mem[b * DD + d] = acc;
}

// ---------------------------------------------------------------
// Word-level attention: ONE WARP per (b, s), online softmax,
// zero shared memory, zero block barriers.
// 25600 warps = 6400 blocks x 4 warps, perfectly packed.
// Lane holds d = 4*lane..4*lane+3 as float4.
// ---------------------------------------------------------------
__global__ void __launch_bounds__(128)
k_word_attn(const int* __restrict__ user_idx,
            const int* __restrict__ uti,
            const float* __restrict__ emb_word,
            const float* __restrict__ w_word,
            const float* __restrict__ b_word) {
    int ws   = blockIdx.x * 4 + (threadIdx.x >> 5);   // global warp = sentence id
    int lane = threadIdx.x & 31;
    int b = ws / SS;
    int s = ws - b * SS;

    float4 m4 = reinterpret_cast<const float4*>(g_mem + b * DD)[lane];

    int u = user_idx[b];
    const int* idxp = uti + ((size_t)u * SS + s) * TT;
    int idx_all = idxp[lane];            // all 32 word indices, one per lane

    float mx = -1e30f, sm = 0.f;
    float4 acc = make_float4(0.f, 0.f, 0.f, 0.f);

#pragma unroll
    for (int m = 0; m < 4; m++) {
        // broadcast this batch's 8 row indices
        int widx[8];
#pragma unroll
        for (int k = 0; k < 8; k++)
            widx[k] = __shfl_sync(0xffffffffu, idx_all, m * 8 + k);

        float4 r[8];
#pragma unroll
        for (int k = 0; k < 8; k++)
            r[k] = reinterpret_cast<const float4*>(emb_word + (size_t)widx[k] * DD)[lane];

        // per-lane partial dots
        float p[8];
#pragma unroll
        for (int k = 0; k < 8; k++)
            p[k] = r[k].x * m4.x + r[k].y * m4.y + r[k].z * m4.z + r[k].w * m4.w;

        // butterflies over bits 4,3 (16 SHFL)
#pragma unroll
        for (int off = 16; off >= 8; off >>= 1) {
#pragma unroll
            for (int k = 0; k < 8; k++)
                p[k] += __shfl_xor_sync(0xffffffffu, p[k], off);
        }
        // merge-exchange down to one score per lane (7 SHFL)
        // lane l ends holding score of row k = 4*bit0(l) + 2*bit1(l) + bit2(l)
        float q0 = merge2(p[0], p[1], 4, lane);
        float q1 = merge2(p[2], p[3], 4, lane);
        float q2 = merge2(p[4], p[5], 4, lane);
        float q3 = merge2(p[6], p[7], 4, lane);
        float r0 = merge2(q0, q1, 2, lane);
        float r1 = merge2(q2, q3, 2, lane);
        float s0 = merge2(r0, r1, 1, lane);

        // batch max over the 8 rows (replicated per 8-lane group)
        float bm = s0;
#pragma unroll
        for (int off = 4; off; off >>= 1)
            bm = fmaxf(bm, __shfl_xor_sync(0xffffffffu, bm, off));

        float nm = fmaxf(mx, bm);
        float scale = __expf(mx - nm);   // first iter: exp(-inf) = 0, state was 0
        float e = __expf(s0 - nm);
        float bs = e;
#pragma unroll
        for (int off = 4; off; off >>= 1)
            bs += __shfl_xor_sync(0xffffffffu, bs, off);

        sm = sm * scale + bs;
        acc.x *= scale; acc.y *= scale; acc.z *= scale; acc.w *= scale;
#pragma unroll
        for (int k = 0; k < 8; k++) {
            int src = ((k & 1) << 2) | (k & 2) | ((k >> 2) & 1);  // lane holding row k
            float wk = __shfl_sync(0xffffffffu, e, src);
            acc.x += wk * r[k].x;
            acc.y += wk * r[k].y;
            acc.z += wk * r[k].z;
            acc.w += wk * r[k].w;
        }
        mx = nm;
    }

    float inv = __fdividef(1.f, sm);
    float4 sd = make_float4(acc.x * inv, acc.y * inv, acc.z * inv, acc.w * inv);
    reinterpret_cast<float4*>(g_sent + ((size_t)b * SS + s) * DD)[lane] = sd;

    // sw = sentence . w_word + b_word
    float4 ww4 = reinterpret_cast<const float4*>(w_word)[lane];
    float pw = sd.x * ww4.x + sd.y * ww4.y + sd.z * ww4.z + sd.w * ww4.w;
#pragma unroll
    for (int o = 16; o; o >>= 1) pw += __shfl_xor_sync(0xffffffffu, pw, o);
    if (lane == 0) g_sw[b * SS + s] = pw + b_word[0];
}

// ---------------------------------------------------------------
// Sentence-level attention + mem update.  grid=B, block=128
// ---------------------------------------------------------------
__global__ void k_sent_attn(const float* __restrict__ w_sent,
                            const float* __restrict__ b_sent) {
    int b = blockIdx.x, tid = threadIdx.x, lane = tid & 31, warp = tid >> 5;
    __shared__ float wred[4];
    __shared__ float swf[SS];
    __shared__ float iw_s;

    float m = g_mem[b * DD + tid];

    // iw = mem . w_sent + b_sent
    float p = m * w_sent[tid];
#pragma unroll
    for (int o = 16; o; o >>= 1) p += __shfl_xor_sync(0xffffffffu, p, o);
    if (lane == 0) wred[warp] = p;
    __syncthreads();
    if (tid == 0) iw_s = wred[0] + wred[1] + wred[2] + wred[3] + b_sent[0];
    __syncthreads();

    // softmax over S of tanh(sw + iw)  (warp 0)
    if (warp == 0) {
        float iw = iw_s;
        float v0 = (lane < SS)      ? tanhf(g_sw[b * SS + lane] + iw)        : -1e30f;
        float v1 = (lane + 32 < SS) ? tanhf(g_sw[b * SS + lane + 32] + iw)   : -1e30f;
        float mx = fmaxf(v0, v1);
#pragma unroll
        for (int o = 16; o; o >>= 1) mx = fmaxf(mx, __shfl_xor_sync(0xffffffffu, mx, o));
        float e0 = (lane < SS)      ? __expf(v0 - mx) : 0.f;
        float e1 = (lane + 32 < SS) ? __expf(v1 - mx) : 0.f;
        float sum = e0 + e1;
#pragma unroll
        for (int o = 16; o; o >>= 1) sum += __shfl_xor_sync(0xffffffffu, sum, o);
        float inv = __fdividef(1.f, sum);
        if (lane < SS)      swf[lane]      = e0 * inv;
        if (lane + 32 < SS) swf[lane + 32] = e1 * inv;
    }
    __syncthreads();

    // mem += sum_s swf[s] * sentence[b,s,:]
    float acc = m;
    const float* sp = g_sent + (size_t)b * SS * DD + tid;
#pragma unroll 5
    for (int s = 0; s < SS; s++) acc += swf[s] * sp[s * DD];
    g_mem[b * DD + tid] = acc;
}

// ---------------------------------------------------------------
// Final stage: ept, friend aggregation + group_idx, alpha MLP, rating.
// grid=B, block=64 (=L)
// ---------------------------------------------------------------
__global__ void k_final(const int* __restrict__ user_idx,
                        const int* __restrict__ item_idx,
                        const float* __restrict__ emb_item,
                        const float* __restrict__ emb_user,
                        const float* __restrict__ W_tr, const float* __restrict__ b_tr,
                        const float* __restrict__ W1,  const float* __restrict__ b1,
                        const float* __restrict__ W2,  const float* __restrict__ b2,
                        const float* __restrict__ W3,  const float* __restrict__ b3,
                        const float* __restrict__ w_aff, const float* __restrict__ b_aff,
                        const int* __restrict__ ufi,
                        float* __restrict__ out) {
    int b = blockIdx.x, l = threadIdx.x, lane = l & 31, warp = l >> 5;
    __shared__ float item_s[LL], a1[32], a2[16], alpha[2];
    __shared__ float upart[2][LL];
    __shared__ float red2[2];
    __shared__ int padc[2];

    float it = emb_item[(size_t)item_idx[b] * LL + l];
    item_s[l] = it;
    float waff_l = w_aff[l];
    float ba = b_aff[0];

    // ept[l] = mem[b] @ W_tr[:, l] + b_tr[l]
    float ept = b_tr[l];
    const float* memp = g_mem + b * DD;
#pragma unroll 8
    for (int d = 0; d < DD; d++) ept += memp[d] * W_tr[d * LL + l];
    __syncthreads();

    // alpha MLP
    if (l < 32) {
        float a = b1[l];
#pragma unroll
        for (int k = 0; k < LL; k++) a += item_s[k] * W1[k * 32 + l];
        a1[l] = 1.f / (1.f + __expf(-a));
    }
    __syncthreads();
    if (l < 16) {
        float a = b2[l];
#pragma unroll
        for (int k = 0; k < 32; k++) a += a1[k] * W2[k * 16 + l];
        a2[l] = 1.f / (1.f + __expf(-a));
    }
    __syncthreads();
    if (l < 2) {
        float a = b3[l];
#pragma unroll
        for (int k = 0; k < 16; k++) a += a2[k] * W3[k * 2 + l];
        alpha[l] = 1.f / (1.f + __expf(-a));
    }

    // friend aggregation: warp w handles friends c = w, w+2, ...
    int u = user_idx[b];
    const int* fp = ufi + (size_t)u * CLIPF;
    float i0 = item_s[lane],       i1 = item_s[lane + 32];
    float w0 = w_aff[lane],        w1 = w_aff[lane + 32];
    float ua0 = 0.f, ua1 = 0.f;
    int pcount = 0;
    for (int c = warp; c < CLIPF; c += 2) {
        int f = fp[c];
        if (f == NF && lane == 0) pcount++;
        const float* fr = emb_user + (size_t)f * LL;
        float f0 = fr[lane], f1 = fr[lane + 32];
        float p = i0 * f0 * w0 + i1 * f1 * w1;
#pragma unroll
        for (int o = 16; o; o >>= 1) p += __shfl_xor_sync(0xffffffffu, p, o);
        float g = 1.f / (1.f + __expf(-(p + ba)));
        if (lane == 0) out[BB + (size_t)b * CLIPF + c] = g;
        ua0 += f0 * g;
        ua1 += f1 * g;
    }
    upart[warp][lane] = ua0;
    upart[warp][lane + 32] = ua1;
    if (lane == 0) padc[warp] = pcount;
    __syncthreads();

    float fn = (float)CLIPF - (float)(padc[0] + padc[1]);
    float ue = (upart[0][l] + upart[1][l]) / fn;

    float vec = alpha[0] * ept + alpha[1] * ue;
    float p = vec * it * waff_l;
#pragma unroll
    for (int o = 16; o; o >>= 1) p += __shfl_xor_sync(0xffffffffu, p, o);
    if (lane == 0) red2[warp] = p;
    __syncthreads();
    if (l == 0) out[b] = 1.f / (1.f + __expf(-(red2[0] + red2[1] + ba)));
}

// ---------------------------------------------------------------
extern "C" void kernel_launch(void* const* d_in, const int* in_sizes, int n_in,
                              void* d_out, int out_size) {
    const int*   user_idx = (const int*)d_in[0];
    const int*   item_idx = (const int*)d_in[1];
    const float* emb_word = (const float*)d_in[2];
    const float* emb_item = (const float*)d_in[3];
    const float* emb_user = (const float*)d_in[4];
    const float* W_mem    = (const float*)d_in[5];
    const float* b_mem    = (const float*)d_in[6];
    const float* w_word   = (const float*)d_in[7];
    const float* b_word   = (const float*)d_in[8];
    const float* w_sent   = (const float*)d_in[9];
    const float* b_sent   = (const float*)d_in[10];
    const float* W_tr     = (const float*)d_in[11];
    const float* b_tr     = (const float*)d_in[12];
    const float* W1       = (const float*)d_in[13];
    const float* b1       = (const float*)d_in[14];
    const float* W2       = (const float*)d_in[15];
    const float* b2       = (const float*)d_in[16];
    const float* W3       = (const float*)d_in[17];
    const float* b3       = (const float*)d_in[18];
    const float* w_aff    = (const float*)d_in[19];
    const float* b_aff    = (const float*)d_in[20];
    const int*   uti      = (const int*)d_in[21];
    const int*   ufi      = (const int*)d_in[22];
    float* out = (float*)d_out;

    k_init_mem<<<BB, DD>>>(item_idx, emb_item, W_mem, b_mem);
    for (int h = 0; h < 2; h++) {
        k_word_attn<<<BB * SS / 4, 128>>>(user_idx, uti, emb_word, w_word, b_word);
        k_sent_attn<<<BB, 128>>>(w_sent, b_sent);
    }
    k_final<<<BB, LL>>>(user_idx, item_idx, emb_item, emb_user,
                        W_tr, b_tr, W1, b1, W2, b2, W3, b3,
                        w_aff, b_aff, ufi, out);
}